// round 16
// baseline (speedup 1.0000x reference)
#include <cuda_runtime.h>
#include <cuda_fp16.h>
#include <cstdint>
#include <math.h>

// ---------------------------------------------------------------------------
// Attention_3856880632117 — fp16-resident single-term HMMA pipeline, v4.
// mma.sync.m16n8k16.f16 + ldmatrix + cp.async (plain sm_103: no tcgen05).
// GEMM hot loop: cp.async(kt+2) issued BEFORE mma(kt) each iteration
// (true prefetch depth 2), 3-stage ring, one sync/chunk, 256 thr,
// 2x4 warps, 64x32 warp tiles, 2 CTAs/SM. nch templated for fixed-K stages.
//
//   Stage 0: cvt x, Wq, Wk, Wv -> fp16 (merged, 2x float4 ILP)
//   Stage 1: q = x Wq^T, k = x Wk^T
//   Stage 2: MERGED: S = q k^T (544 triangular tiles) + vt = Wv x^T (512)
//   Stage 3: causal softmax — warp-per-row, paired I/O
//   Stage 4: out = P vt^T (k-extent clipped, globally heavy-first)
// ---------------------------------------------------------------------------

#define NB 4
#define NT 2048
#define NCH 1024
#define NXT (NB * NT)

typedef unsigned short u16;

// Scratch (allocation-free rule: __device__ globals).
__device__ u16  g_x16[(size_t)NXT * NCH];
__device__ u16  g_w16[3][(size_t)NCH * NCH];
__device__ u16  g_q16[(size_t)NXT * NCH];
__device__ u16  g_k16[(size_t)NXT * NCH];
__device__ u16  g_vt16[(size_t)NCH * NXT];       // [c][b*T + t]
__device__ float g_s [(size_t)NB * NT * NT];     // fp32 scores
__device__ u16  g_p16[(size_t)NB * NT * NT];     // fp16 probs

// ---------------- primitives ------------------------------------------------
__device__ __forceinline__ void ldsm4(uint32_t* r, uint32_t addr) {
    asm volatile("ldmatrix.sync.aligned.m8n8.x4.shared.b16 {%0,%1,%2,%3}, [%4];"
                 : "=r"(r[0]), "=r"(r[1]), "=r"(r[2]), "=r"(r[3]) : "r"(addr));
}
__device__ __forceinline__ void mma_f16(float* c, const uint32_t* a, const uint32_t* b) {
    asm volatile(
        "mma.sync.aligned.m16n8k16.row.col.f32.f16.f16.f32 "
        "{%0,%1,%2,%3},{%4,%5,%6,%7},{%8,%9},{%0,%1,%2,%3};"
        : "+f"(c[0]), "+f"(c[1]), "+f"(c[2]), "+f"(c[3])
        : "r"(a[0]), "r"(a[1]), "r"(a[2]), "r"(a[3]), "r"(b[0]), "r"(b[1]));
}
__device__ __forceinline__ uint32_t smem_u32(const void* p) {
    uint32_t a;
    asm("{ .reg .u64 t; cvta.to.shared.u64 t, %1; cvt.u32.u64 %0, t; }"
        : "=r"(a) : "l"(p));
    return a;
}
__device__ __forceinline__ uint32_t pack_f16x2(float hi, float lo) {
    uint32_t r;
    asm("cvt.rn.f16x2.f32 %0, %1, %2;" : "=r"(r) : "f"(hi), "f"(lo));
    return r;
}
__device__ __forceinline__ void cp16(uint32_t dst, const void* src) {
    asm volatile("cp.async.cg.shared.global [%0], [%1], 16;" :: "r"(dst), "l"(src));
}
#define CP_COMMIT() asm volatile("cp.async.commit_group;" ::: "memory")
#define CP_WAIT(n)  asm volatile("cp.async.wait_group %0;" :: "n"(n) : "memory")

// ---------------------------------------------------------------------------
// SMEM (K-chunk 64): fp16 tiles 128 rows x 128B payload, 144B pitch
// (conflict-free ldmatrix). 2 regions (A | B) per stage, 3 stages.
// ---------------------------------------------------------------------------
#define PITCHB     144
#define REGION     18432
#define STAGE_H    (2 * REGION)          // 36864
#define NSTAGE     3
#define SMEM_H     (NSTAGE * STAGE_H)    // 110592

// ======================= fp16 single-term core ===============================
// NCHT > 0: compile-time chunk count (fully unrolled); NCHT == 0: dynamic.
template <bool EPI16, int NCHT>
__device__ __forceinline__ void mma_core(
    const u16* __restrict__ At, int lda,
    const u16* __restrict__ Bt, int ldb,
    void* __restrict__ Ct, int ldc,
    int nch_dyn)
{
    extern __shared__ char smraw[];
    const uint32_t smu = smem_u32(smraw);
    const int nch = (NCHT > 0) ? NCHT : nch_dyn;

    const int tid  = threadIdx.x;
    const int lane = tid & 31;
    const int wid  = tid >> 5;
    const int wm   = wid >> 2;
    const int wn   = wid & 3;

    const int row0 = tid >> 3;   // 0..31 (+32*i)
    const int seg  = tid & 7;    // 16B segment within 128B payload

    const uint32_t aRowByte = (uint32_t)(lane & 15) * PITCHB + (uint32_t)(lane >> 4) * 16;
    const uint32_t bRowByte = (uint32_t)(((lane >> 4) << 3) + (lane & 7)) * PITCHB
                            + (uint32_t)((lane >> 3) & 1) * 16;

    float acc[4][4][4];
    #pragma unroll
    for (int mf = 0; mf < 4; ++mf)
        #pragma unroll
        for (int nf = 0; nf < 4; ++nf)
            #pragma unroll
            for (int q = 0; q < 4; ++q) acc[mf][nf][q] = 0.0f;

    auto load_chunk = [&](int kt, int buf) {
        const int kb = kt * 64;
        const uint32_t sb = smu + (uint32_t)buf * STAGE_H;
        #pragma unroll
        for (int i = 0; i < 4; ++i) {
            const int r = row0 + i * 32;
            const uint32_t d = sb + (uint32_t)r * PITCHB + (uint32_t)seg * 16;
            cp16(d,          At + (size_t)r * lda + kb + seg * 8);
            cp16(d + REGION, Bt + (size_t)r * ldb + kb + seg * 8);
        }
        CP_COMMIT();
    };

    auto mma_chunk = [&](int buf) {
        const uint32_t sbase = smu + (uint32_t)buf * STAGE_H;
        #pragma unroll
        for (int sk = 0; sk < 4; ++sk) {
            uint32_t ah[4][4], bh[4][2];
            const uint32_t aBase = sbase + (uint32_t)(wm * 64) * PITCHB + aRowByte
                                 + (uint32_t)sk * 32;
            #pragma unroll
            for (int mf = 0; mf < 4; ++mf)
                ldsm4(ah[mf], aBase + (uint32_t)mf * (16 * PITCHB));
            const uint32_t bBase = sbase + REGION + (uint32_t)(wn * 32) * PITCHB
                                 + bRowByte + (uint32_t)sk * 32;
            #pragma unroll
            for (int p = 0; p < 2; ++p) {
                uint32_t t[4];
                ldsm4(t, bBase + (uint32_t)p * (16 * PITCHB));
                bh[2 * p][0] = t[0]; bh[2 * p][1] = t[1];
                bh[2 * p + 1][0] = t[2]; bh[2 * p + 1][1] = t[3];
            }
            #pragma unroll
            for (int mf = 0; mf < 4; ++mf)
                #pragma unroll
                for (int nf = 0; nf < 4; ++nf)
                    mma_f16(acc[mf][nf], ah[mf], bh[nf]);
        }
    };

    // 3-stage ring, one barrier per chunk. Loads for kt+2 are issued BEFORE
    // mma(kt): buffer (kt+2)%3 == (kt-1)%3 was last read at iter kt-1 and the
    // barrier this iteration proves all warps are past it, while mma reads
    // buffer kt%3 (distinct mod 3). This keeps 2 chunks of cp.async in flight
    // during MMA issue instead of <1.
    load_chunk(0, 0);
    if (nch > 1) load_chunk(1, 1);
    if (NCHT > 0) {
        #pragma unroll
        for (int kt = 0; kt < NCHT; ++kt) {
            if (kt + 1 < NCHT) { CP_WAIT(1); } else { CP_WAIT(0); }
            __syncthreads();
            if (kt + 2 < NCHT)
                load_chunk(kt + 2, (kt + 2) % NSTAGE);
            mma_chunk(kt % NSTAGE);
        }
    } else {
        #pragma unroll 4
        for (int kt = 0; kt < nch; ++kt) {
            if (kt + 1 < nch) { CP_WAIT(1); } else { CP_WAIT(0); }
            __syncthreads();
            if (kt + 2 < nch)
                load_chunk(kt + 2, (kt + 2) % NSTAGE);
            mma_chunk(kt % NSTAGE);
        }
    }

    #pragma unroll
    for (int mf = 0; mf < 4; ++mf) {
        #pragma unroll
        for (int nf = 0; nf < 4; ++nf) {
            const int row = wm * 64 + mf * 16 + (lane >> 2);
            const int col = wn * 32 + nf * 8 + (lane & 3) * 2;
            if (EPI16) {
                u16* C = (u16*)Ct;
                *reinterpret_cast<uint32_t*>(C + (size_t)row * ldc + col) =
                    pack_f16x2(acc[mf][nf][1], acc[mf][nf][0]);
                *reinterpret_cast<uint32_t*>(C + (size_t)(row + 8) * ldc + col) =
                    pack_f16x2(acc[mf][nf][3], acc[mf][nf][2]);
            } else {
                float* C = (float*)Ct;
                *reinterpret_cast<float2*>(C + (size_t)row * ldc + col) =
                    make_float2(acc[mf][nf][0], acc[mf][nf][1]);
                *reinterpret_cast<float2*>(C + (size_t)(row + 8) * ldc + col) =
                    make_float2(acc[mf][nf][2], acc[mf][nf][3]);
            }
        }
    }
}

// Stage 0: merged fp32 -> fp16 convert, 2x float4 per thread per iteration.
#define N4X ((NXT * NCH) / 4)
#define N4W ((NCH * NCH) / 4)
__global__ __launch_bounds__(256)
void cvt_all(const float* __restrict__ x,  const float* __restrict__ Wq,
             const float* __restrict__ Wk, const float* __restrict__ Wv)
{
    const int total = N4X + 3 * N4W;
    for (int i0 = (blockIdx.x * 256 + threadIdx.x) * 2; i0 < total;
         i0 += gridDim.x * 512) {
        #pragma unroll
        for (int u = 0; u < 2; ++u) {
            const int i = i0 + u;
            if (i >= total) break;
            const float* src; u16* dst; int j;
            if (i < N4X)              { src = x;  dst = g_x16;    j = i; }
            else if (i < N4X + N4W)   { src = Wq; dst = g_w16[0]; j = i - N4X; }
            else if (i < N4X + 2*N4W) { src = Wk; dst = g_w16[1]; j = i - N4X - N4W; }
            else                      { src = Wv; dst = g_w16[2]; j = i - N4X - 2*N4W; }
            float4 v = reinterpret_cast<const float4*>(src)[j];
            reinterpret_cast<uint2*>(dst)[j] =
                make_uint2(pack_f16x2(v.y, v.x), pack_f16x2(v.w, v.z));
        }
    }
}

// Stage 1: q, k projections. grid = (64, 8, 2). Fully unrolled nch=16.
__global__ __launch_bounds__(256, 2)
void qk_proj(int dummy)
{
    const int bx = blockIdx.x, by = blockIdx.y, z = blockIdx.z;
    u16* o = (z == 0) ? g_q16 : g_k16;
    mma_core<true, 16>(g_x16 + (size_t)bx * 128 * NCH, NCH,
                       g_w16[z] + (size_t)by * 128 * NCH, NCH,
                       o + (size_t)bx * 128 * NCH + by * 128, NCH, 16);
}

// Stage 2 MERGED: S = q k^T (544 triangular tiles) + vt = Wv x^T (512 tiles).
// grid.x = 1056; all CTAs nch = 16 (fully unrolled).
__global__ __launch_bounds__(256, 2)
void qk_vt(int dummy)
{
    const int idx = blockIdx.x;
    if (idx < 544) {
        const int b = idx / 136;
        const int t = idx - b * 136;
        int by = (int)((sqrtf(8.0f * (float)t + 1.0f) - 1.0f) * 0.5f);
        while ((by + 1) * (by + 2) / 2 <= t) ++by;     // guard fp rounding
        while (by * (by + 1) / 2 > t) --by;
        const int bx = t - by * (by + 1) / 2;          // bx <= by
        mma_core<false, 16>(g_q16 + (size_t)b * NT * NCH + (size_t)by * 128 * NCH, NCH,
                            g_k16 + (size_t)b * NT * NCH + (size_t)bx * 128 * NCH, NCH,
                            g_s + (size_t)b * NT * NT + (size_t)by * 128 * NT
                                + bx * 128, NT, 16);
    } else {
        const int v = idx - 544;           // 0..511
        const int bx = v & 63;             // t-tile (of 8192)
        const int by = v >> 6;             // c-tile (of 1024)
        mma_core<true, 16>(g_w16[2] + (size_t)by * 128 * NCH, NCH,
                           g_x16 + (size_t)bx * 128 * NCH, NCH,
                           g_vt16 + (size_t)by * 128 * NXT + bx * 128, NXT, 16);
    }
}

// Stage 3: causal softmax — warp-per-row, float2 loads / uint32 packed stores.
// grid=(NT/4, NB), 128 threads (4 warps).
__global__ __launch_bounds__(128)
void softmax_causal(float scale)
{
    const int lane = threadIdx.x & 31;
    const int i = blockIdx.x * 4 + (threadIdx.x >> 5);
    const size_t ro = ((size_t)blockIdx.y * NT + i) * NT;
    const float* row = g_s + ro;
    const int len = i + 1;

    float2 v[32];
    float m = -INFINITY;
    #pragma unroll
    for (int k = 0; k < 32; ++k) {
        const int j = 2 * (lane + 32 * k);
        float2 p = *reinterpret_cast<const float2*>(row + j);
        p.x = (j     < len) ? p.x : -INFINITY;
        p.y = (j + 1 < len) ? p.y : -INFINITY;
        v[k] = p;
        m = fmaxf(m, fmaxf(p.x, p.y));
    }
    #pragma unroll
    for (int o = 16; o > 0; o >>= 1) m = fmaxf(m, __shfl_xor_sync(0xffffffffu, m, o));

    float s = 0.0f;
    #pragma unroll
    for (int k = 0; k < 32; ++k) {
        float e0 = __expf((v[k].x - m) * scale);   // -inf -> 0
        float e1 = __expf((v[k].y - m) * scale);
        v[k].x = e0; v[k].y = e1;
        s += e0 + e1;
    }
    #pragma unroll
    for (int o = 16; o > 0; o >>= 1) s += __shfl_xor_sync(0xffffffffu, s, o);
    const float inv = 1.0f / s;

    const int jend = ((i >> 7) + 1) << 7;   // zero-pad to 128-row block boundary
    #pragma unroll
    for (int k = 0; k < 32; ++k) {
        const int j = 2 * (lane + 32 * k);
        if (j < jend)
            *reinterpret_cast<uint32_t*>(g_p16 + ro + j) =
                pack_f16x2(v[k].y * inv, v[k].x * inv);
    }
}

// Stage 4: out = P vt^T, k-extent clipped, GLOBALLY heavy-first:
// grid = (8, NB, 16); z slowest-varying -> by = 15 - z.
__global__ __launch_bounds__(256, 2)
void pv_mma(float* __restrict__ out)
{
    const int bx = blockIdx.x, b = blockIdx.y;
    const int by = 15 - (int)blockIdx.z;         // heavy first, all batches
    mma_core<false, 0>(g_p16 + (size_t)b * NT * NT + (size_t)by * 128 * NT, NT,
                       g_vt16 + (size_t)bx * 128 * NXT + (size_t)b * NT, NXT,
                       out + (size_t)b * NT * NCH + (size_t)by * 128 * NCH + bx * 128,
                       NCH, (by + 1) * 2);
}

extern "C" void kernel_launch(void* const* d_in, const int* in_sizes, int n_in,
                              void* d_out, int out_size)
{
    const float* x  = (const float*)d_in[0];
    const float* Wq = (const float*)d_in[1];
    const float* Wk = (const float*)d_in[2];
    const float* Wv = (const float*)d_in[3];
    float* out = (float*)d_out;

    static bool attr_done = false;
    if (!attr_done) {
        cudaFuncSetAttribute(qk_proj, cudaFuncAttributeMaxDynamicSharedMemorySize, SMEM_H);
        cudaFuncSetAttribute(qk_vt,   cudaFuncAttributeMaxDynamicSharedMemorySize, SMEM_H);
        cudaFuncSetAttribute(pv_mma,  cudaFuncAttributeMaxDynamicSharedMemorySize, SMEM_H);
        attr_done = true;
    }

    dim3 blk(256), blk128(128);
    cvt_all<<<2048, blk>>>(x, Wq, Wk, Wv);
    qk_proj<<<dim3(64, 8, 2), blk, SMEM_H>>>(0);
    qk_vt<<<1056, blk, SMEM_H>>>(0);
    softmax_causal<<<dim3(NT / 4, NB), blk128>>>(1.0f / 32.0f);   // 1024^-0.5
    pv_mma<<<dim3(8, NB, 16), blk, SMEM_H>>>(out);
}

// round 17
// speedup vs baseline: 1.0518x; 1.0518x over previous
#include <cuda_runtime.h>
#include <cuda_fp16.h>
#include <cstdint>
#include <math.h>

// ---------------------------------------------------------------------------
// Attention_3856880632117 — fp16-resident single-term HMMA pipeline, v5
// (R15 GEMM core verbatim — R16's load-before-mma reorder regressed and is
// reverted; softmax now skips loading the masked tail).
// mma.sync.m16n8k16.f16 + ldmatrix + cp.async (plain sm_103: no tcgen05).
// GEMM hot loop: sync -> mma(kt) -> cp.async(kt+2), 3-stage ring, one
// sync/chunk, 256 thr, 2x4 warps, 64x32 warp tiles, 2 CTAs/SM.
//
//   Stage 0: cvt x, Wq, Wk, Wv -> fp16 (merged, 2x float4 ILP)
//   Stage 1: q = x Wq^T, k = x Wk^T
//   Stage 2: MERGED: S = q k^T (544 triangular tiles) + vt = Wv x^T (512)
//   Stage 3: causal softmax — warp-per-row, guarded loads (causal prefix only)
//   Stage 4: out = P vt^T (k-extent clipped, globally heavy-first)
// ---------------------------------------------------------------------------

#define NB 4
#define NT 2048
#define NCH 1024
#define NXT (NB * NT)

typedef unsigned short u16;

// Scratch (allocation-free rule: __device__ globals).
__device__ u16  g_x16[(size_t)NXT * NCH];
__device__ u16  g_w16[3][(size_t)NCH * NCH];
__device__ u16  g_q16[(size_t)NXT * NCH];
__device__ u16  g_k16[(size_t)NXT * NCH];
__device__ u16  g_vt16[(size_t)NCH * NXT];       // [c][b*T + t]
__device__ float g_s [(size_t)NB * NT * NT];     // fp32 scores
__device__ u16  g_p16[(size_t)NB * NT * NT];     // fp16 probs

// ---------------- primitives ------------------------------------------------
__device__ __forceinline__ void ldsm4(uint32_t* r, uint32_t addr) {
    asm volatile("ldmatrix.sync.aligned.m8n8.x4.shared.b16 {%0,%1,%2,%3}, [%4];"
                 : "=r"(r[0]), "=r"(r[1]), "=r"(r[2]), "=r"(r[3]) : "r"(addr));
}
__device__ __forceinline__ void mma_f16(float* c, const uint32_t* a, const uint32_t* b) {
    asm volatile(
        "mma.sync.aligned.m16n8k16.row.col.f32.f16.f16.f32 "
        "{%0,%1,%2,%3},{%4,%5,%6,%7},{%8,%9},{%0,%1,%2,%3};"
        : "+f"(c[0]), "+f"(c[1]), "+f"(c[2]), "+f"(c[3])
        : "r"(a[0]), "r"(a[1]), "r"(a[2]), "r"(a[3]), "r"(b[0]), "r"(b[1]));
}
__device__ __forceinline__ uint32_t smem_u32(const void* p) {
    uint32_t a;
    asm("{ .reg .u64 t; cvta.to.shared.u64 t, %1; cvt.u32.u64 %0, t; }"
        : "=r"(a) : "l"(p));
    return a;
}
__device__ __forceinline__ uint32_t pack_f16x2(float hi, float lo) {
    uint32_t r;
    asm("cvt.rn.f16x2.f32 %0, %1, %2;" : "=r"(r) : "f"(hi), "f"(lo));
    return r;
}
__device__ __forceinline__ void cp16(uint32_t dst, const void* src) {
    asm volatile("cp.async.cg.shared.global [%0], [%1], 16;" :: "r"(dst), "l"(src));
}
#define CP_COMMIT() asm volatile("cp.async.commit_group;" ::: "memory")
#define CP_WAIT(n)  asm volatile("cp.async.wait_group %0;" :: "n"(n) : "memory")

// ---------------------------------------------------------------------------
// SMEM (K-chunk 64): fp16 tiles 128 rows x 128B payload, 144B pitch
// (conflict-free ldmatrix). 2 regions (A | B) per stage, 3 stages.
// ---------------------------------------------------------------------------
#define PITCHB     144
#define REGION     18432
#define STAGE_H    (2 * REGION)          // 36864
#define NSTAGE     3
#define SMEM_H     (NSTAGE * STAGE_H)    // 110592

// ======================= fp16 single-term core ===============================
// NCHT > 0: compile-time chunk count (fully unrolled); NCHT == 0: dynamic.
template <bool EPI16, int NCHT>
__device__ __forceinline__ void mma_core(
    const u16* __restrict__ At, int lda,
    const u16* __restrict__ Bt, int ldb,
    void* __restrict__ Ct, int ldc,
    int nch_dyn)
{
    extern __shared__ char smraw[];
    const uint32_t smu = smem_u32(smraw);
    const int nch = (NCHT > 0) ? NCHT : nch_dyn;

    const int tid  = threadIdx.x;
    const int lane = tid & 31;
    const int wid  = tid >> 5;
    const int wm   = wid >> 2;
    const int wn   = wid & 3;

    const int row0 = tid >> 3;   // 0..31 (+32*i)
    const int seg  = tid & 7;    // 16B segment within 128B payload

    const uint32_t aRowByte = (uint32_t)(lane & 15) * PITCHB + (uint32_t)(lane >> 4) * 16;
    const uint32_t bRowByte = (uint32_t)(((lane >> 4) << 3) + (lane & 7)) * PITCHB
                            + (uint32_t)((lane >> 3) & 1) * 16;

    float acc[4][4][4];
    #pragma unroll
    for (int mf = 0; mf < 4; ++mf)
        #pragma unroll
        for (int nf = 0; nf < 4; ++nf)
            #pragma unroll
            for (int q = 0; q < 4; ++q) acc[mf][nf][q] = 0.0f;

    auto load_chunk = [&](int kt, int buf) {
        const int kb = kt * 64;
        const uint32_t sb = smu + (uint32_t)buf * STAGE_H;
        #pragma unroll
        for (int i = 0; i < 4; ++i) {
            const int r = row0 + i * 32;
            const uint32_t d = sb + (uint32_t)r * PITCHB + (uint32_t)seg * 16;
            cp16(d,          At + (size_t)r * lda + kb + seg * 8);
            cp16(d + REGION, Bt + (size_t)r * ldb + kb + seg * 8);
        }
        CP_COMMIT();
    };

    auto mma_chunk = [&](int buf) {
        const uint32_t sbase = smu + (uint32_t)buf * STAGE_H;
        #pragma unroll
        for (int sk = 0; sk < 4; ++sk) {
            uint32_t ah[4][4], bh[4][2];
            const uint32_t aBase = sbase + (uint32_t)(wm * 64) * PITCHB + aRowByte
                                 + (uint32_t)sk * 32;
            #pragma unroll
            for (int mf = 0; mf < 4; ++mf)
                ldsm4(ah[mf], aBase + (uint32_t)mf * (16 * PITCHB));
            const uint32_t bBase = sbase + REGION + (uint32_t)(wn * 32) * PITCHB
                                 + bRowByte + (uint32_t)sk * 32;
            #pragma unroll
            for (int p = 0; p < 2; ++p) {
                uint32_t t[4];
                ldsm4(t, bBase + (uint32_t)p * (16 * PITCHB));
                bh[2 * p][0] = t[0]; bh[2 * p][1] = t[1];
                bh[2 * p + 1][0] = t[2]; bh[2 * p + 1][1] = t[3];
            }
            #pragma unroll
            for (int mf = 0; mf < 4; ++mf)
                #pragma unroll
                for (int nf = 0; nf < 4; ++nf)
                    mma_f16(acc[mf][nf], ah[mf], bh[nf]);
        }
    };

    // 3-stage ring, one barrier per chunk, prefetch distance 2 (R15 order:
    // mma first, then next-next load — measured faster than load-first).
    load_chunk(0, 0);
    if (nch > 1) load_chunk(1, 1);
    if (NCHT > 0) {
        #pragma unroll
        for (int kt = 0; kt < NCHT; ++kt) {
            if (kt + 1 < NCHT) { CP_WAIT(1); } else { CP_WAIT(0); }
            __syncthreads();
            mma_chunk(kt % NSTAGE);
            if (kt + 2 < NCHT)
                load_chunk(kt + 2, (kt + 2) % NSTAGE);
        }
    } else {
        for (int kt = 0; kt < nch; ++kt) {
            if (kt + 1 < nch) { CP_WAIT(1); } else { CP_WAIT(0); }
            __syncthreads();
            mma_chunk(kt % NSTAGE);
            if (kt + 2 < nch)
                load_chunk(kt + 2, (kt + 2) % NSTAGE);
        }
    }

    #pragma unroll
    for (int mf = 0; mf < 4; ++mf) {
        #pragma unroll
        for (int nf = 0; nf < 4; ++nf) {
            const int row = wm * 64 + mf * 16 + (lane >> 2);
            const int col = wn * 32 + nf * 8 + (lane & 3) * 2;
            if (EPI16) {
                u16* C = (u16*)Ct;
                *reinterpret_cast<uint32_t*>(C + (size_t)row * ldc + col) =
                    pack_f16x2(acc[mf][nf][1], acc[mf][nf][0]);
                *reinterpret_cast<uint32_t*>(C + (size_t)(row + 8) * ldc + col) =
                    pack_f16x2(acc[mf][nf][3], acc[mf][nf][2]);
            } else {
                float* C = (float*)Ct;
                *reinterpret_cast<float2*>(C + (size_t)row * ldc + col) =
                    make_float2(acc[mf][nf][0], acc[mf][nf][1]);
                *reinterpret_cast<float2*>(C + (size_t)(row + 8) * ldc + col) =
                    make_float2(acc[mf][nf][2], acc[mf][nf][3]);
            }
        }
    }
}

// Stage 0: merged fp32 -> fp16 convert, 2x float4 per thread per iteration.
#define N4X ((NXT * NCH) / 4)
#define N4W ((NCH * NCH) / 4)
__global__ __launch_bounds__(256)
void cvt_all(const float* __restrict__ x,  const float* __restrict__ Wq,
             const float* __restrict__ Wk, const float* __restrict__ Wv)
{
    const int total = N4X + 3 * N4W;
    for (int i0 = (blockIdx.x * 256 + threadIdx.x) * 2; i0 < total;
         i0 += gridDim.x * 512) {
        #pragma unroll
        for (int u = 0; u < 2; ++u) {
            const int i = i0 + u;
            if (i >= total) break;
            const float* src; u16* dst; int j;
            if (i < N4X)              { src = x;  dst = g_x16;    j = i; }
            else if (i < N4X + N4W)   { src = Wq; dst = g_w16[0]; j = i - N4X; }
            else if (i < N4X + 2*N4W) { src = Wk; dst = g_w16[1]; j = i - N4X - N4W; }
            else                      { src = Wv; dst = g_w16[2]; j = i - N4X - 2*N4W; }
            float4 v = reinterpret_cast<const float4*>(src)[j];
            reinterpret_cast<uint2*>(dst)[j] =
                make_uint2(pack_f16x2(v.y, v.x), pack_f16x2(v.w, v.z));
        }
    }
}

// Stage 1: q, k projections. grid = (64, 8, 2). Fully unrolled nch=16.
__global__ __launch_bounds__(256, 2)
void qk_proj(int dummy)
{
    const int bx = blockIdx.x, by = blockIdx.y, z = blockIdx.z;
    u16* o = (z == 0) ? g_q16 : g_k16;
    mma_core<true, 16>(g_x16 + (size_t)bx * 128 * NCH, NCH,
                       g_w16[z] + (size_t)by * 128 * NCH, NCH,
                       o + (size_t)bx * 128 * NCH + by * 128, NCH, 16);
}

// Stage 2 MERGED: S = q k^T (544 triangular tiles) + vt = Wv x^T (512 tiles).
// grid.x = 1056; all CTAs nch = 16 (fully unrolled).
__global__ __launch_bounds__(256, 2)
void qk_vt(int dummy)
{
    const int idx = blockIdx.x;
    if (idx < 544) {
        const int b = idx / 136;
        const int t = idx - b * 136;
        int by = (int)((sqrtf(8.0f * (float)t + 1.0f) - 1.0f) * 0.5f);
        while ((by + 1) * (by + 2) / 2 <= t) ++by;     // guard fp rounding
        while (by * (by + 1) / 2 > t) --by;
        const int bx = t - by * (by + 1) / 2;          // bx <= by
        mma_core<false, 16>(g_q16 + (size_t)b * NT * NCH + (size_t)by * 128 * NCH, NCH,
                            g_k16 + (size_t)b * NT * NCH + (size_t)bx * 128 * NCH, NCH,
                            g_s + (size_t)b * NT * NT + (size_t)by * 128 * NT
                                + bx * 128, NT, 16);
    } else {
        const int v = idx - 544;           // 0..511
        const int bx = v & 63;             // t-tile (of 8192)
        const int by = v >> 6;             // c-tile (of 1024)
        mma_core<true, 16>(g_w16[2] + (size_t)by * 128 * NCH, NCH,
                           g_x16 + (size_t)bx * 128 * NCH, NCH,
                           g_vt16 + (size_t)by * 128 * NXT + bx * 128, NXT, 16);
    }
}

// Stage 3: causal softmax — warp-per-row; loads ONLY the causal prefix
// (masked tail never touches memory), float2 loads / uint32 packed stores.
// grid=(NT/4, NB), 128 threads (4 warps).
__global__ __launch_bounds__(128)
void softmax_causal(float scale)
{
    const int lane = threadIdx.x & 31;
    const int i = blockIdx.x * 4 + (threadIdx.x >> 5);
    const size_t ro = ((size_t)blockIdx.y * NT + i) * NT;
    const float* row = g_s + ro;
    const int len = i + 1;

    float2 v[32];
    float m = -INFINITY;
    #pragma unroll
    for (int k = 0; k < 32; ++k) {
        const int j = 2 * (lane + 32 * k);
        float2 p;
        if (j < len) {                       // guarded: skip masked tail
            p = *reinterpret_cast<const float2*>(row + j);
            if (j + 1 >= len) p.y = -INFINITY;
        } else {
            p.x = -INFINITY; p.y = -INFINITY;
        }
        v[k] = p;
        m = fmaxf(m, fmaxf(p.x, p.y));
    }
    #pragma unroll
    for (int o = 16; o > 0; o >>= 1) m = fmaxf(m, __shfl_xor_sync(0xffffffffu, m, o));

    float s = 0.0f;
    #pragma unroll
    for (int k = 0; k < 32; ++k) {
        float e0 = __expf((v[k].x - m) * scale);   // -inf -> 0
        float e1 = __expf((v[k].y - m) * scale);
        v[k].x = e0; v[k].y = e1;
        s += e0 + e1;
    }
    #pragma unroll
    for (int o = 16; o > 0; o >>= 1) s += __shfl_xor_sync(0xffffffffu, s, o);
    const float inv = 1.0f / s;

    const int jend = ((i >> 7) + 1) << 7;   // zero-pad to 128-row block boundary
    #pragma unroll
    for (int k = 0; k < 32; ++k) {
        const int j = 2 * (lane + 32 * k);
        if (j < jend)
            *reinterpret_cast<uint32_t*>(g_p16 + ro + j) =
                pack_f16x2(v[k].y * inv, v[k].x * inv);
    }
}

// Stage 4: out = P vt^T, k-extent clipped, GLOBALLY heavy-first:
// grid = (8, NB, 16); z slowest-varying -> by = 15 - z.
__global__ __launch_bounds__(256, 2)
void pv_mma(float* __restrict__ out)
{
    const int bx = blockIdx.x, b = blockIdx.y;
    const int by = 15 - (int)blockIdx.z;         // heavy first, all batches
    mma_core<false, 0>(g_p16 + (size_t)b * NT * NT + (size_t)by * 128 * NT, NT,
                       g_vt16 + (size_t)bx * 128 * NXT + (size_t)b * NT, NXT,
                       out + (size_t)b * NT * NCH + (size_t)by * 128 * NCH + bx * 128,
                       NCH, (by + 1) * 2);
}

extern "C" void kernel_launch(void* const* d_in, const int* in_sizes, int n_in,
                              void* d_out, int out_size)
{
    const float* x  = (const float*)d_in[0];
    const float* Wq = (const float*)d_in[1];
    const float* Wk = (const float*)d_in[2];
    const float* Wv = (const float*)d_in[3];
    float* out = (float*)d_out;

    static bool attr_done = false;
    if (!attr_done) {
        cudaFuncSetAttribute(qk_proj, cudaFuncAttributeMaxDynamicSharedMemorySize, SMEM_H);
        cudaFuncSetAttribute(qk_vt,   cudaFuncAttributeMaxDynamicSharedMemorySize, SMEM_H);
        cudaFuncSetAttribute(pv_mma,  cudaFuncAttributeMaxDynamicSharedMemorySize, SMEM_H);
        attr_done = true;
    }

    dim3 blk(256), blk128(128);
    cvt_all<<<2048, blk>>>(x, Wq, Wk, Wv);
    qk_proj<<<dim3(64, 8, 2), blk, SMEM_H>>>(0);
    qk_vt<<<1056, blk, SMEM_H>>>(0);
    softmax_causal<<<dim3(NT / 4, NB), blk128>>>(1.0f / 32.0f);   // 1024^-0.5
    pv_mma<<<dim3(8, NB, 16), blk, SMEM_H>>>(out);
}